// round 4
// baseline (speedup 1.0000x reference)
#include <cuda_runtime.h>
#include <cstdint>

static constexpr int MAXN = 100352;

// Scratch (static device globals: allocation-free per harness rules)
__device__ float g_h0[MAXN];     // dropout1(x)
__device__ float g_deg[MAXN];    // in-degree (float)
__device__ float g_dinv[MAXN];   // deg^-1/2 (0 if deg==0)
__device__ float g_hd[MAXN];     // h0 * dinv  (gathered by pass1)
__device__ float g_acc1[MAXN];   // edge-sum for conv1
__device__ float g_sd[MAXN];     // s2 * dinv  (gathered by pass2)
__device__ float g_acc2[MAXN];   // edge-sum for conv2

// keep  <=>  uniform(bits) < float32(0.4)  <=>  bits < 0x66666800
#define KEEP_THRESH 0x66666800u

__host__ __device__ __forceinline__ void tf2x32(uint32_t k0, uint32_t k1,
                                                uint32_t x0, uint32_t x1,
                                                uint32_t& o0, uint32_t& o1) {
    uint32_t ks2 = k0 ^ k1 ^ 0x1BD11BDAu;
    x0 += k0; x1 += k1;
#define TF_ROT(d) { x0 += x1; x1 = (x1 << (d)) | (x1 >> (32 - (d))); x1 ^= x0; }
    TF_ROT(13) TF_ROT(15) TF_ROT(26) TF_ROT(6)   x0 += k1;  x1 += ks2 + 1u;
    TF_ROT(17) TF_ROT(29) TF_ROT(16) TF_ROT(24)  x0 += ks2; x1 += k0 + 2u;
    TF_ROT(13) TF_ROT(15) TF_ROT(26) TF_ROT(6)   x0 += k0;  x1 += k1 + 3u;
    TF_ROT(17) TF_ROT(29) TF_ROT(16) TF_ROT(24)  x0 += k1;  x1 += ks2 + 4u;
    TF_ROT(13) TF_ROT(15) TF_ROT(26) TF_ROT(6)   x0 += ks2; x1 += k0 + 5u;
#undef TF_ROT
    o0 = x0; o1 = x1;
}

// partitionable counter-mode bits: lane0 ^ lane1 of threefry(key, (0, i))
__device__ __forceinline__ uint32_t rbits32(uint32_t k0, uint32_t k1, uint32_t i) {
    uint32_t a, b;
    tf2x32(k0, k1, 0u, i, a, b);
    return a ^ b;
}

// ---------------- node kernels ----------------

__global__ __launch_bounds__(256) void k_init(const float* __restrict__ x, int N,
                                              uint32_t k0, uint32_t k1) {
    int n = blockIdx.x * blockDim.x + threadIdx.x;
    if (n >= N) return;
    uint32_t bits = rbits32(k0, k1, (uint32_t)n);
    g_h0[n]   = (bits < KEEP_THRESH) ? (x[n] / 0.4f) : 0.0f;
    g_deg[n]  = 0.0f;
    g_acc1[n] = 0.0f;
    g_acc2[n] = 0.0f;
}

__global__ __launch_bounds__(256) void k_hd(int N) {
    int n = blockIdx.x * blockDim.x + threadIdx.x;
    if (n >= N) return;
    float v  = g_deg[n];
    float di = (v > 0.0f) ? rsqrtf(v) : 0.0f;
    g_dinv[n] = di;
    g_hd[n]   = g_h0[n] * di;
}

// conv1 epilogue + relu + dropout2 (inline threefry) + W2 contraction
__global__ __launch_bounds__(256) void k_s2(const float* __restrict__ W1,
                                            const float* __restrict__ b1,
                                            const float* __restrict__ W2, int N,
                                            uint32_t k0, uint32_t k1) {
    int n = blockIdx.x * blockDim.x + threadIdx.x;
    if (n >= N) return;
    float a = g_acc1[n] * g_dinv[n];   // conv1 segment value (b1 added per channel)
    uint32_t base = (uint32_t)n * 16u;
    float s = 0.0f;
#pragma unroll
    for (int c = 0; c < 16; ++c) {
        uint32_t bits = rbits32(k0, k1, base + (uint32_t)c);
        float h = fmaf(a, __ldg(&W1[c]), __ldg(&b1[c]));
        h = fmaxf(h, 0.0f);
        if (bits < KEEP_THRESH)
            s = fmaf(h / 0.4f, __ldg(&W2[c]), s);
    }
    g_sd[n] = s * g_dinv[n];
}

__global__ __launch_bounds__(256) void k_final(float* __restrict__ out,
                                               const float* __restrict__ b2, int N) {
    int n = blockIdx.x * blockDim.x + threadIdx.x;
    if (n >= N) return;
    out[n] = fmaf(g_acc2[n], g_dinv[n], __ldg(&b2[0]));
}

// ---------------- edge kernels (8 edges/thread) ----------------

__global__ __launch_bounds__(256) void k_deg(const int* __restrict__ dst,
                                             int EV, int E) {
    int i = blockIdx.x * blockDim.x + threadIdx.x;
    if (i < EV) {
        const int4* d4 = reinterpret_cast<const int4*>(dst);
        int4 a = __ldcs(&d4[i * 2]);
        int4 b = __ldcs(&d4[i * 2 + 1]);
        atomicAdd(&g_deg[a.x], 1.0f);
        atomicAdd(&g_deg[a.y], 1.0f);
        atomicAdd(&g_deg[a.z], 1.0f);
        atomicAdd(&g_deg[a.w], 1.0f);
        atomicAdd(&g_deg[b.x], 1.0f);
        atomicAdd(&g_deg[b.y], 1.0f);
        atomicAdd(&g_deg[b.z], 1.0f);
        atomicAdd(&g_deg[b.w], 1.0f);
    }
    if (i == 0) {
        for (int e = EV * 8; e < E; ++e) atomicAdd(&g_deg[dst[e]], 1.0f);
    }
}

template <const float* SRC_ARR, float* ACC_ARR>
__global__ __launch_bounds__(256) void k_scatter(const int* __restrict__ src,
                                                 const int* __restrict__ dst,
                                                 int EV, int E) {
    int i = blockIdx.x * blockDim.x + threadIdx.x;
    if (i < EV) {
        const int4* s4 = reinterpret_cast<const int4*>(src);
        const int4* d4 = reinterpret_cast<const int4*>(dst);
        int4 sa = __ldcs(&s4[i * 2]);
        int4 sb = __ldcs(&s4[i * 2 + 1]);
        int4 da = __ldcs(&d4[i * 2]);
        int4 db = __ldcs(&d4[i * 2 + 1]);
        // front-batch the 8 spread gathers for MLP
        float v0 = __ldg(&SRC_ARR[sa.x]);
        float v1 = __ldg(&SRC_ARR[sa.y]);
        float v2 = __ldg(&SRC_ARR[sa.z]);
        float v3 = __ldg(&SRC_ARR[sa.w]);
        float v4 = __ldg(&SRC_ARR[sb.x]);
        float v5 = __ldg(&SRC_ARR[sb.y]);
        float v6 = __ldg(&SRC_ARR[sb.z]);
        float v7 = __ldg(&SRC_ARR[sb.w]);
        atomicAdd(&ACC_ARR[da.x], v0);
        atomicAdd(&ACC_ARR[da.y], v1);
        atomicAdd(&ACC_ARR[da.z], v2);
        atomicAdd(&ACC_ARR[da.w], v3);
        atomicAdd(&ACC_ARR[db.x], v4);
        atomicAdd(&ACC_ARR[db.y], v5);
        atomicAdd(&ACC_ARR[db.z], v6);
        atomicAdd(&ACC_ARR[db.w], v7);
    }
    if (i == 0) {
        for (int e = EV * 8; e < E; ++e)
            atomicAdd(&ACC_ARR[dst[e]], SRC_ARR[src[e]]);
    }
}

// explicit instantiations via wrappers (template-on-pointer needs linkage: use
// plain kernels instead for safety)
__global__ __launch_bounds__(256) void k_pass1(const int* __restrict__ src,
                                               const int* __restrict__ dst,
                                               int EV, int E) {
    int i = blockIdx.x * blockDim.x + threadIdx.x;
    if (i < EV) {
        const int4* s4 = reinterpret_cast<const int4*>(src);
        const int4* d4 = reinterpret_cast<const int4*>(dst);
        int4 sa = __ldcs(&s4[i * 2]);
        int4 sb = __ldcs(&s4[i * 2 + 1]);
        int4 da = __ldcs(&d4[i * 2]);
        int4 db = __ldcs(&d4[i * 2 + 1]);
        float v0 = __ldg(&g_hd[sa.x]);
        float v1 = __ldg(&g_hd[sa.y]);
        float v2 = __ldg(&g_hd[sa.z]);
        float v3 = __ldg(&g_hd[sa.w]);
        float v4 = __ldg(&g_hd[sb.x]);
        float v5 = __ldg(&g_hd[sb.y]);
        float v6 = __ldg(&g_hd[sb.z]);
        float v7 = __ldg(&g_hd[sb.w]);
        atomicAdd(&g_acc1[da.x], v0);
        atomicAdd(&g_acc1[da.y], v1);
        atomicAdd(&g_acc1[da.z], v2);
        atomicAdd(&g_acc1[da.w], v3);
        atomicAdd(&g_acc1[db.x], v4);
        atomicAdd(&g_acc1[db.y], v5);
        atomicAdd(&g_acc1[db.z], v6);
        atomicAdd(&g_acc1[db.w], v7);
    }
    if (i == 0) {
        for (int e = EV * 8; e < E; ++e)
            atomicAdd(&g_acc1[dst[e]], g_hd[src[e]]);
    }
}

__global__ __launch_bounds__(256) void k_pass2(const int* __restrict__ src,
                                               const int* __restrict__ dst,
                                               int EV, int E) {
    int i = blockIdx.x * blockDim.x + threadIdx.x;
    if (i < EV) {
        const int4* s4 = reinterpret_cast<const int4*>(src);
        const int4* d4 = reinterpret_cast<const int4*>(dst);
        int4 sa = __ldcs(&s4[i * 2]);
        int4 sb = __ldcs(&s4[i * 2 + 1]);
        int4 da = __ldcs(&d4[i * 2]);
        int4 db = __ldcs(&d4[i * 2 + 1]);
        float v0 = __ldg(&g_sd[sa.x]);
        float v1 = __ldg(&g_sd[sa.y]);
        float v2 = __ldg(&g_sd[sa.z]);
        float v3 = __ldg(&g_sd[sa.w]);
        float v4 = __ldg(&g_sd[sb.x]);
        float v5 = __ldg(&g_sd[sb.y]);
        float v6 = __ldg(&g_sd[sb.z]);
        float v7 = __ldg(&g_sd[sb.w]);
        atomicAdd(&g_acc2[da.x], v0);
        atomicAdd(&g_acc2[da.y], v1);
        atomicAdd(&g_acc2[da.z], v2);
        atomicAdd(&g_acc2[da.w], v3);
        atomicAdd(&g_acc2[db.x], v4);
        atomicAdd(&g_acc2[db.y], v5);
        atomicAdd(&g_acc2[db.z], v6);
        atomicAdd(&g_acc2[db.w], v7);
    }
    if (i == 0) {
        for (int e = EV * 8; e < E; ++e)
            atomicAdd(&g_acc2[dst[e]], g_sd[src[e]]);
    }
}

// ---------------- host ----------------

extern "C" void kernel_launch(void* const* d_in, const int* in_sizes, int n_in,
                              void* d_out, int out_size) {
    const float* x   = (const float*)d_in[0];
    const int*   ei  = (const int*)d_in[1];      // edge_index is int32 (JAX x64 disabled)
    const float* W1  = (const float*)d_in[2];
    const float* b1  = (const float*)d_in[3];
    const float* W2  = (const float*)d_in[4];
    const float* b2  = (const float*)d_in[5];

    int N = in_sizes[0];
    int E = in_sizes[1] >> 1;
    if (N > MAXN || N <= 0 || E <= 0) return;

    const int* src = ei;
    const int* dst = ei + E;

    // key(42) -> (0, 42); partitionable split: key_i = threefry(parent, (0, i))
    uint32_t k1a, k1b, k2a, k2b;
    tf2x32(0u, 42u, 0u, 0u, k1a, k1b);
    tf2x32(0u, 42u, 0u, 1u, k2a, k2b);

    const int TPB = 256;
    int nb = (N + TPB - 1) / TPB;
    int EV = E / 8;                         // 8 edges per thread (2x int4 loads)
    int eb = (EV + TPB - 1) / TPB;
    if (eb == 0) eb = 1;

    k_init <<<nb, TPB>>>(x, N, k1a, k1b);
    k_deg  <<<eb, TPB>>>(dst, EV, E);
    k_hd   <<<nb, TPB>>>(N);
    k_pass1<<<eb, TPB>>>(src, dst, EV, E);
    k_s2   <<<nb, TPB>>>(W1, b1, W2, N, k2a, k2b);
    k_pass2<<<eb, TPB>>>(src, dst, EV, E);
    k_final<<<nb, TPB>>>((float*)d_out, b2, N);
}

// round 5
// speedup vs baseline: 1.2887x; 1.2887x over previous
#include <cuda_runtime.h>
#include <cuda_fp16.h>
#include <cstdint>

static constexpr int MAXN = 100352;

// Scratch (static device globals: allocation-free per harness rules)
__device__ float  g_h0[MAXN];     // dropout1(x)
__device__ float  g_deg[MAXN];    // in-degree (float)
__device__ float  g_dinv[MAXN];   // deg^-1/2 (0 if deg==0)
__device__ __half g_hd16[MAXN];   // h0 * dinv   (fp16: fits in 228KB L1)
__device__ float  g_acc1[MAXN];   // edge-sum for conv1
__device__ __half g_sd16[MAXN];   // s2 * dinv   (fp16)
__device__ float  g_acc2[MAXN];   // edge-sum for conv2

// keep  <=>  uniform(bits) < float32(0.4)  <=>  bits < 0x66666800
#define KEEP_THRESH 0x66666800u

__host__ __device__ __forceinline__ void tf2x32(uint32_t k0, uint32_t k1,
                                                uint32_t x0, uint32_t x1,
                                                uint32_t& o0, uint32_t& o1) {
    uint32_t ks2 = k0 ^ k1 ^ 0x1BD11BDAu;
    x0 += k0; x1 += k1;
#define TF_ROT(d) { x0 += x1; x1 = (x1 << (d)) | (x1 >> (32 - (d))); x1 ^= x0; }
    TF_ROT(13) TF_ROT(15) TF_ROT(26) TF_ROT(6)   x0 += k1;  x1 += ks2 + 1u;
    TF_ROT(17) TF_ROT(29) TF_ROT(16) TF_ROT(24)  x0 += ks2; x1 += k0 + 2u;
    TF_ROT(13) TF_ROT(15) TF_ROT(26) TF_ROT(6)   x0 += k0;  x1 += k1 + 3u;
    TF_ROT(17) TF_ROT(29) TF_ROT(16) TF_ROT(24)  x0 += k1;  x1 += ks2 + 4u;
    TF_ROT(13) TF_ROT(15) TF_ROT(26) TF_ROT(6)   x0 += ks2; x1 += k0 + 5u;
#undef TF_ROT
    o0 = x0; o1 = x1;
}

// partitionable counter-mode bits: lane0 ^ lane1 of threefry(key, (0, i))
__device__ __forceinline__ uint32_t rbits32(uint32_t k0, uint32_t k1, uint32_t i) {
    uint32_t a, b;
    tf2x32(k0, k1, 0u, i, a, b);
    return a ^ b;
}

// ---------------- node kernels ----------------

__global__ __launch_bounds__(256) void k_init(const float* __restrict__ x, int N,
                                              uint32_t k0, uint32_t k1) {
    int n = blockIdx.x * blockDim.x + threadIdx.x;
    if (n >= N) return;
    uint32_t bits = rbits32(k0, k1, (uint32_t)n);
    g_h0[n]   = (bits < KEEP_THRESH) ? (x[n] / 0.4f) : 0.0f;
    g_deg[n]  = 0.0f;
    g_acc1[n] = 0.0f;
    g_acc2[n] = 0.0f;
}

__global__ __launch_bounds__(256) void k_hd(int N) {
    int n = blockIdx.x * blockDim.x + threadIdx.x;
    if (n >= N) return;
    float v  = g_deg[n];
    float di = (v > 0.0f) ? rsqrtf(v) : 0.0f;
    g_dinv[n]  = di;
    g_hd16[n]  = __float2half_rn(g_h0[n] * di);
}

// conv1 epilogue + relu + dropout2 (inline threefry) + W2 contraction
__global__ __launch_bounds__(256) void k_s2(const float* __restrict__ W1,
                                            const float* __restrict__ b1,
                                            const float* __restrict__ W2, int N,
                                            uint32_t k0, uint32_t k1) {
    int n = blockIdx.x * blockDim.x + threadIdx.x;
    if (n >= N) return;
    float a = g_acc1[n] * g_dinv[n];   // conv1 segment value (b1 added per channel)
    uint32_t base = (uint32_t)n * 16u;
    float s = 0.0f;
#pragma unroll
    for (int c = 0; c < 16; ++c) {
        uint32_t bits = rbits32(k0, k1, base + (uint32_t)c);
        float h = fmaf(a, __ldg(&W1[c]), __ldg(&b1[c]));
        h = fmaxf(h, 0.0f);
        if (bits < KEEP_THRESH)
            s = fmaf(h / 0.4f, __ldg(&W2[c]), s);
    }
    g_sd16[n] = __float2half_rn(s * g_dinv[n]);
}

__global__ __launch_bounds__(256) void k_final(float* __restrict__ out,
                                               const float* __restrict__ b2, int N) {
    int n = blockIdx.x * blockDim.x + threadIdx.x;
    if (n >= N) return;
    out[n] = fmaf(g_acc2[n], g_dinv[n], __ldg(&b2[0]));
}

// ---------------- edge kernels (8 edges/thread) ----------------

__global__ __launch_bounds__(256) void k_deg(const int* __restrict__ dst,
                                             int EV, int E) {
    int i = blockIdx.x * blockDim.x + threadIdx.x;
    if (i < EV) {
        const int4* d4 = reinterpret_cast<const int4*>(dst);
        int4 a = __ldcs(&d4[i * 2]);
        int4 b = __ldcs(&d4[i * 2 + 1]);
        atomicAdd(&g_deg[a.x], 1.0f);
        atomicAdd(&g_deg[a.y], 1.0f);
        atomicAdd(&g_deg[a.z], 1.0f);
        atomicAdd(&g_deg[a.w], 1.0f);
        atomicAdd(&g_deg[b.x], 1.0f);
        atomicAdd(&g_deg[b.y], 1.0f);
        atomicAdd(&g_deg[b.z], 1.0f);
        atomicAdd(&g_deg[b.w], 1.0f);
    }
    if (i == 0) {
        for (int e = EV * 8; e < E; ++e) atomicAdd(&g_deg[dst[e]], 1.0f);
    }
}

__global__ __launch_bounds__(256) void k_pass1(const int* __restrict__ src,
                                               const int* __restrict__ dst,
                                               int EV, int E) {
    int i = blockIdx.x * blockDim.x + threadIdx.x;
    if (i < EV) {
        const int4* s4 = reinterpret_cast<const int4*>(src);
        const int4* d4 = reinterpret_cast<const int4*>(dst);
        int4 sa = __ldcs(&s4[i * 2]);
        int4 sb = __ldcs(&s4[i * 2 + 1]);
        int4 da = __ldcs(&d4[i * 2]);
        int4 db = __ldcs(&d4[i * 2 + 1]);
        // front-batched fp16 gathers (array fits in L1)
        float v0 = __half2float(g_hd16[sa.x]);
        float v1 = __half2float(g_hd16[sa.y]);
        float v2 = __half2float(g_hd16[sa.z]);
        float v3 = __half2float(g_hd16[sa.w]);
        float v4 = __half2float(g_hd16[sb.x]);
        float v5 = __half2float(g_hd16[sb.y]);
        float v6 = __half2float(g_hd16[sb.z]);
        float v7 = __half2float(g_hd16[sb.w]);
        // 60% of hd values are exact zeros (dropout) -> skip those REDs
        if (v0 != 0.0f) atomicAdd(&g_acc1[da.x], v0);
        if (v1 != 0.0f) atomicAdd(&g_acc1[da.y], v1);
        if (v2 != 0.0f) atomicAdd(&g_acc1[da.z], v2);
        if (v3 != 0.0f) atomicAdd(&g_acc1[da.w], v3);
        if (v4 != 0.0f) atomicAdd(&g_acc1[db.x], v4);
        if (v5 != 0.0f) atomicAdd(&g_acc1[db.y], v5);
        if (v6 != 0.0f) atomicAdd(&g_acc1[db.z], v6);
        if (v7 != 0.0f) atomicAdd(&g_acc1[db.w], v7);
    }
    if (i == 0) {
        for (int e = EV * 8; e < E; ++e) {
            float v = __half2float(g_hd16[src[e]]);
            if (v != 0.0f) atomicAdd(&g_acc1[dst[e]], v);
        }
    }
}

__global__ __launch_bounds__(256) void k_pass2(const int* __restrict__ src,
                                               const int* __restrict__ dst,
                                               int EV, int E) {
    int i = blockIdx.x * blockDim.x + threadIdx.x;
    if (i < EV) {
        const int4* s4 = reinterpret_cast<const int4*>(src);
        const int4* d4 = reinterpret_cast<const int4*>(dst);
        int4 sa = __ldcs(&s4[i * 2]);
        int4 sb = __ldcs(&s4[i * 2 + 1]);
        int4 da = __ldcs(&d4[i * 2]);
        int4 db = __ldcs(&d4[i * 2 + 1]);
        float v0 = __half2float(g_sd16[sa.x]);
        float v1 = __half2float(g_sd16[sa.y]);
        float v2 = __half2float(g_sd16[sa.z]);
        float v3 = __half2float(g_sd16[sa.w]);
        float v4 = __half2float(g_sd16[sb.x]);
        float v5 = __half2float(g_sd16[sb.y]);
        float v6 = __half2float(g_sd16[sb.z]);
        float v7 = __half2float(g_sd16[sb.w]);
        if (v0 != 0.0f) atomicAdd(&g_acc2[da.x], v0);
        if (v1 != 0.0f) atomicAdd(&g_acc2[da.y], v1);
        if (v2 != 0.0f) atomicAdd(&g_acc2[da.z], v2);
        if (v3 != 0.0f) atomicAdd(&g_acc2[da.w], v3);
        if (v4 != 0.0f) atomicAdd(&g_acc2[db.x], v4);
        if (v5 != 0.0f) atomicAdd(&g_acc2[db.y], v5);
        if (v6 != 0.0f) atomicAdd(&g_acc2[db.z], v6);
        if (v7 != 0.0f) atomicAdd(&g_acc2[db.w], v7);
    }
    if (i == 0) {
        for (int e = EV * 8; e < E; ++e) {
            float v = __half2float(g_sd16[src[e]]);
            if (v != 0.0f) atomicAdd(&g_acc2[dst[e]], v);
        }
    }
}

// ---------------- host ----------------

extern "C" void kernel_launch(void* const* d_in, const int* in_sizes, int n_in,
                              void* d_out, int out_size) {
    const float* x   = (const float*)d_in[0];
    const int*   ei  = (const int*)d_in[1];      // edge_index is int32 (JAX x64 disabled)
    const float* W1  = (const float*)d_in[2];
    const float* b1  = (const float*)d_in[3];
    const float* W2  = (const float*)d_in[4];
    const float* b2  = (const float*)d_in[5];

    int N = in_sizes[0];
    int E = in_sizes[1] >> 1;
    if (N > MAXN || N <= 0 || E <= 0) return;

    const int* src = ei;
    const int* dst = ei + E;

    // key(42) -> (0, 42); partitionable split: key_i = threefry(parent, (0, i))
    uint32_t k1a, k1b, k2a, k2b;
    tf2x32(0u, 42u, 0u, 0u, k1a, k1b);
    tf2x32(0u, 42u, 0u, 1u, k2a, k2b);

    const int TPB = 256;
    int nb = (N + TPB - 1) / TPB;
    int EV = E / 8;                         // 8 edges per thread (2x int4 loads)
    int eb = (EV + TPB - 1) / TPB;
    if (eb == 0) eb = 1;

    k_init <<<nb, TPB>>>(x, N, k1a, k1b);
    k_deg  <<<eb, TPB>>>(dst, EV, E);
    k_hd   <<<nb, TPB>>>(N);
    k_pass1<<<eb, TPB>>>(src, dst, EV, E);
    k_s2   <<<nb, TPB>>>(W1, b1, W2, N, k2a, k2b);
    k_pass2<<<eb, TPB>>>(src, dst, EV, E);
    k_final<<<nb, TPB>>>((float*)d_out, b2, N);
}